// round 14
// baseline (speedup 1.0000x reference)
#include <cuda_runtime.h>
#include <cuda_fp16.h>
#include <math.h>

#define NN 100000
#define DD 128
#define EE 1600000
#define BB 100000

// ---------------- scratch, double-buffered per domain (no allocations) ------
__device__ __align__(16) __half g_tmph[2][(size_t)NN * DD]; // dinv-scaled GEMM out
__device__ __align__(16) __half g_h1[2][(size_t)NN * DD];   // relu(layer1 out), fp16
__device__ __align__(16) __half g_h[2][(size_t)NN * DD];    // layer2 out (fp16)
__device__ float  g_dinv[2][NN];
__device__ int    g_deg[2][NN];
__device__ int    g_rowptr[2][NN + 1];
__device__ int    g_cursor[2][NN];
__device__ int    g_col[2][EE];
__device__ int    g_bsum[2][128];
__device__ int    g_boff[2][128];
__device__ double g_acc[8];   // bases 0 (src) and 3 (tgt)

// ---------------- tiny init ----------------
__global__ void k_zero_acc() {
    int i = threadIdx.x;
    if (i < 8) g_acc[i] = 0.0;
}

__global__ void k_zero_deg(int* __restrict__ deg) {
    int i = blockIdx.x * blockDim.x + threadIdx.x;
    if (i < NN) deg[i] = 0;
}

__global__ void k_deg(const int* __restrict__ dst, int* __restrict__ deg) {
    int e4 = blockIdx.x * blockDim.x + threadIdx.x;
    if (e4 < EE / 4) {
        int4 d = ((const int4*)dst)[e4];
        atomicAdd(&deg[d.x], 1);
        atomicAdd(&deg[d.y], 1);
        atomicAdd(&deg[d.z], 1);
        atomicAdd(&deg[d.w], 1);
    }
}

__global__ void k_dinv(const int* __restrict__ deg, float* __restrict__ dinv) {
    int i = blockIdx.x * blockDim.x + threadIdx.x;
    if (i < NN) dinv[i] = rsqrtf((float)deg[i] + 1.0f);  // +1 = self loop
}

__global__ void k_scan1(const int* __restrict__ deg, int* __restrict__ rowptr,
                        int* __restrict__ bsum) {
    __shared__ int s_warp[32];
    int tid = threadIdx.x;
    int lane = tid & 31, wid = tid >> 5;
    int i = blockIdx.x * 1024 + tid;
    int v = (i < NN) ? deg[i] : 0;
    int x = v;
#pragma unroll
    for (int o = 1; o < 32; o <<= 1) {
        int y = __shfl_up_sync(0xffffffffu, x, o);
        if (lane >= o) x += y;
    }
    if (lane == 31) s_warp[wid] = x;
    __syncthreads();
    if (wid == 0) {
        int w = s_warp[lane];
#pragma unroll
        for (int o = 1; o < 32; o <<= 1) {
            int y = __shfl_up_sync(0xffffffffu, w, o);
            if (lane >= o) w += y;
        }
        s_warp[lane] = w;
    }
    __syncthreads();
    int excl = (wid ? s_warp[wid - 1] : 0) + x - v;
    if (i < NN) rowptr[i] = excl;
    if (tid == 1023) bsum[blockIdx.x] = s_warp[31];
}

__global__ void k_scan2(const int* __restrict__ bsum, int* __restrict__ boff,
                        int* __restrict__ rowptr, int nblk) {
    int lane = threadIdx.x;
    int carry = 0;
    for (int base = 0; base < nblk; base += 32) {
        int idx = base + lane;
        int v = (idx < nblk) ? bsum[idx] : 0;
        int x = v;
#pragma unroll
        for (int o = 1; o < 32; o <<= 1) {
            int y = __shfl_up_sync(0xffffffffu, x, o);
            if (lane >= o) x += y;
        }
        if (idx < nblk) boff[idx] = carry + x - v;
        carry += __shfl_sync(0xffffffffu, x, 31);
    }
    if (lane == 0) rowptr[NN] = carry;
}

__global__ void k_scan3(int* __restrict__ rowptr, const int* __restrict__ boff,
                        int* __restrict__ cursor) {
    int i = blockIdx.x * blockDim.x + threadIdx.x;
    if (i < NN) {
        int r = rowptr[i] + boff[i >> 10];
        rowptr[i] = r;
        cursor[i] = r;
    }
}

__global__ void k_fill(const int* __restrict__ src, const int* __restrict__ dst,
                       int* __restrict__ cursor, int* __restrict__ col) {
    int e4 = blockIdx.x * blockDim.x + threadIdx.x;
    if (e4 < EE / 4) {
        int4 s = ((const int4*)src)[e4];
        int4 d = ((const int4*)dst)[e4];
        int p;
        p = atomicAdd(&cursor[d.x], 1); col[p] = s.x;
        p = atomicAdd(&cursor[d.y], 1); col[p] = s.y;
        p = atomicAdd(&cursor[d.z], 1); col[p] = s.z;
        p = atomicAdd(&cursor[d.w], 1); col[p] = s.w;
    }
}

// ---------------- gather aggregation (deep-MLP inner loop) ----------------
__device__ __forceinline__ void acc_u2(uint2 u, float4& acc) {
    float2 fa = __half22float2(*(__half2*)&u.x);
    float2 fb = __half22float2(*(__half2*)&u.y);
    acc.x += fa.x; acc.y += fa.y; acc.z += fb.x; acc.w += fb.y;
}

// MODE 1: fp16 + relu (feeds gemm2). MODE 2: fp16 (enc).
template <int MODE>
__global__ __launch_bounds__(256) void k_gather(const __half* __restrict__ tmp,
                                                const float* __restrict__ bias,
                                                void* __restrict__ outv,
                                                const int* __restrict__ rowptr,
                                                const int* __restrict__ col,
                                                const float* __restrict__ dinv) {
    int node = blockIdx.x * 8 + (threadIdx.x >> 5);
    int lane = threadIdx.x & 31;
    if (node >= NN) return;
    int beg = rowptr[node];
    int end = rowptr[node + 1];
    const uint2* t2 = (const uint2*)tmp;
    float4 acc = make_float4(0.f, 0.f, 0.f, 0.f);
    for (int base = beg; base < end; base += 32) {
        int n = min(32, end - base);
        int s = (lane < n) ? col[base + lane] : 0;
        int i = 0;
        // 8 rows in flight: batch the index broadcasts and the LDGs, then accumulate
        for (; i + 8 <= n; i += 8) {
            int r0 = __shfl_sync(0xffffffffu, s, i + 0);
            int r1 = __shfl_sync(0xffffffffu, s, i + 1);
            int r2 = __shfl_sync(0xffffffffu, s, i + 2);
            int r3 = __shfl_sync(0xffffffffu, s, i + 3);
            int r4 = __shfl_sync(0xffffffffu, s, i + 4);
            int r5 = __shfl_sync(0xffffffffu, s, i + 5);
            int r6 = __shfl_sync(0xffffffffu, s, i + 6);
            int r7 = __shfl_sync(0xffffffffu, s, i + 7);
            uint2 v0 = t2[r0 * 32 + lane];
            uint2 v1 = t2[r1 * 32 + lane];
            uint2 v2 = t2[r2 * 32 + lane];
            uint2 v3 = t2[r3 * 32 + lane];
            uint2 v4 = t2[r4 * 32 + lane];
            uint2 v5 = t2[r5 * 32 + lane];
            uint2 v6 = t2[r6 * 32 + lane];
            uint2 v7 = t2[r7 * 32 + lane];
            acc_u2(v0, acc); acc_u2(v1, acc); acc_u2(v2, acc); acc_u2(v3, acc);
            acc_u2(v4, acc); acc_u2(v5, acc); acc_u2(v6, acc); acc_u2(v7, acc);
        }
        if (i + 4 <= n) {
            int r0 = __shfl_sync(0xffffffffu, s, i + 0);
            int r1 = __shfl_sync(0xffffffffu, s, i + 1);
            int r2 = __shfl_sync(0xffffffffu, s, i + 2);
            int r3 = __shfl_sync(0xffffffffu, s, i + 3);
            uint2 v0 = t2[r0 * 32 + lane];
            uint2 v1 = t2[r1 * 32 + lane];
            uint2 v2 = t2[r2 * 32 + lane];
            uint2 v3 = t2[r3 * 32 + lane];
            acc_u2(v0, acc); acc_u2(v1, acc); acc_u2(v2, acc); acc_u2(v3, acc);
            i += 4;
        }
        for (; i < n; i++) {
            int r = __shfl_sync(0xffffffffu, s, i);
            acc_u2(t2[r * 32 + lane], acc);
        }
    }
    acc_u2(t2[node * 32 + lane], acc);   // self-loop term (tmp' pre-scaled)
    float di = dinv[node];
    float4 b = ((const float4*)bias)[lane];
    float4 o;
    o.x = fmaf(di, acc.x, b.x);
    o.y = fmaf(di, acc.y, b.y);
    o.z = fmaf(di, acc.z, b.z);
    o.w = fmaf(di, acc.w, b.w);
    if (MODE == 1) {
        o.x = fmaxf(o.x, 0.f); o.y = fmaxf(o.y, 0.f);
        o.z = fmaxf(o.z, 0.f); o.w = fmaxf(o.w, 0.f);
    }
    uint2 u;
    __half2 h;
    h = __floats2half2_rn(o.x, o.y); u.x = *(unsigned*)&h;
    h = __floats2half2_rn(o.z, o.w); u.y = *(unsigned*)&h;
    ((uint2*)outv)[node * 32 + lane] = u;
}

// ------- GEMM (HFMA2): C_half[r,:] = dinv[r] * (A[r,:] @ W) ----------------
// fp16 tiles; half2 accumulators within each 16-K chunk, promoted to fp32.
// AHALF: A rows are fp16 (h1); else fp32 (feats).
template <bool AHALF>
__global__ __launch_bounds__(256, 2) void k_gemm(const void* __restrict__ Av,
                                                 const float* __restrict__ W,
                                                 __half* __restrict__ C,
                                                 const float* __restrict__ dinv) {
    __shared__ __half sW[16 * 128];   // [k][n], fp16
    __shared__ __half sA[16 * 136];   // [k][row], fp16, padded stride
    int tid = threadIdx.x;
    int r0 = blockIdx.x * 128;
    int tx = tid & 15, ty = tid >> 4;

    int a_row = tid >> 1, a_k8 = (tid & 1) << 3;
    int w_kr0 = tid >> 5, w_c40 = (tid & 31) << 2;
    int w_kr1 = (tid + 256) >> 5, w_c41 = ((tid + 256) & 31) << 2;

    __half a_st[8];
    float4 w_st[2];

    auto load_chunk = [&](int kk) {
        int gr = r0 + a_row;
        if (AHALF) {
            const __half* Ah = (const __half*)Av;
            uint4 u = make_uint4(0u, 0u, 0u, 0u);
            if (gr < NN) u = *(const uint4*)&Ah[(size_t)gr * DD + kk + a_k8];
            *(uint4*)a_st = u;
        } else {
            const float* Af = (const float*)Av;
            float4 a0 = make_float4(0.f, 0.f, 0.f, 0.f);
            float4 a1 = make_float4(0.f, 0.f, 0.f, 0.f);
            if (gr < NN) {
                a0 = *(const float4*)&Af[(size_t)gr * DD + kk + a_k8];
                a1 = *(const float4*)&Af[(size_t)gr * DD + kk + a_k8 + 4];
            }
            __half2 h;
            h = __floats2half2_rn(a0.x, a0.y); *(__half2*)&a_st[0] = h;
            h = __floats2half2_rn(a0.z, a0.w); *(__half2*)&a_st[2] = h;
            h = __floats2half2_rn(a1.x, a1.y); *(__half2*)&a_st[4] = h;
            h = __floats2half2_rn(a1.z, a1.w); *(__half2*)&a_st[6] = h;
        }
        w_st[0] = *(const float4*)&W[(size_t)(kk + w_kr0) * DD + w_c40];
        w_st[1] = *(const float4*)&W[(size_t)(kk + w_kr1) * DD + w_c41];
    };

    auto store_chunk = [&]() {
#pragma unroll
        for (int j = 0; j < 8; j++) sA[(a_k8 + j) * 136 + a_row] = a_st[j];
        uint2 u;
        __half2 h;
        h = __floats2half2_rn(w_st[0].x, w_st[0].y); u.x = *(unsigned*)&h;
        h = __floats2half2_rn(w_st[0].z, w_st[0].w); u.y = *(unsigned*)&h;
        *(uint2*)&sW[w_kr0 * 128 + w_c40] = u;
        h = __floats2half2_rn(w_st[1].x, w_st[1].y); u.x = *(unsigned*)&h;
        h = __floats2half2_rn(w_st[1].z, w_st[1].w); u.y = *(unsigned*)&h;
        *(uint2*)&sW[w_kr1 * 128 + w_c41] = u;
    };

    float facc[8][8];
#pragma unroll
    for (int m = 0; m < 8; m++)
#pragma unroll
        for (int n = 0; n < 8; n++) facc[m][n] = 0.f;

    load_chunk(0);
    for (int c = 0; c < 8; c++) {
        __syncthreads();
        store_chunk();
        __syncthreads();
        if (c < 7) load_chunk((c + 1) * 16);

        __half2 acc2[8][4];
#pragma unroll
        for (int m = 0; m < 8; m++)
#pragma unroll
            for (int np = 0; np < 4; np++)
                acc2[m][np] = __floats2half2_rn(0.f, 0.f);

#pragma unroll
        for (int k2 = 0; k2 < 16; k2++) {
            uint4 av = *(uint4*)&sA[k2 * 136 + ty * 8];
            uint2 u0 = *(uint2*)&sW[k2 * 128 + tx * 4];
            uint2 u1 = *(uint2*)&sW[k2 * 128 + 64 + tx * 4];
            __half2 wv[4];
            wv[0] = *(__half2*)&u0.x;
            wv[1] = *(__half2*)&u0.y;
            wv[2] = *(__half2*)&u1.x;
            wv[3] = *(__half2*)&u1.y;
            __half2 ap[4];
            ap[0] = *(__half2*)&av.x;
            ap[1] = *(__half2*)&av.y;
            ap[2] = *(__half2*)&av.z;
            ap[3] = *(__half2*)&av.w;
#pragma unroll
            for (int mp = 0; mp < 4; mp++) {
                __half2 alo = __half2half2(__low2half(ap[mp]));
                __half2 ahi = __half2half2(__high2half(ap[mp]));
#pragma unroll
                for (int np = 0; np < 4; np++) {
                    acc2[2 * mp + 0][np] = __hfma2(alo, wv[np], acc2[2 * mp + 0][np]);
                    acc2[2 * mp + 1][np] = __hfma2(ahi, wv[np], acc2[2 * mp + 1][np]);
                }
            }
        }
#pragma unroll
        for (int m = 0; m < 8; m++)
#pragma unroll
            for (int np = 0; np < 4; np++) {
                float2 f = __half22float2(acc2[m][np]);
                facc[m][2 * np + 0] += f.x;
                facc[m][2 * np + 1] += f.y;
            }
    }

#pragma unroll
    for (int m = 0; m < 8; m++) {
        int gr = r0 + ty * 8 + m;
        if (gr < NN) {
            float di = dinv[gr];
            uint2 u0, u1;
            __half2 h;
            h = __floats2half2_rn(facc[m][0] * di, facc[m][1] * di); u0.x = *(unsigned*)&h;
            h = __floats2half2_rn(facc[m][2] * di, facc[m][3] * di); u0.y = *(unsigned*)&h;
            h = __floats2half2_rn(facc[m][4] * di, facc[m][5] * di); u1.x = *(unsigned*)&h;
            h = __floats2half2_rn(facc[m][6] * di, facc[m][7] * di); u1.y = *(unsigned*)&h;
            *(uint2*)&C[(size_t)gr * DD + tx * 4] = u0;
            *(uint2*)&C[(size_t)gr * DD + 64 + tx * 4] = u1;
        }
    }
}

// ---------------- fused loss: one warp per (user,item) pair ----------------
__device__ __forceinline__ float dot4(float4 a, float4 b) {
    return a.x * b.x + a.y * b.y + a.z * b.z + a.w * b.w;
}

__device__ __forceinline__ float4 ld_half4(const uint2* p, int idx) {
    uint2 u = p[idx];
    float2 fa = __half22float2(*(__half2*)&u.x);
    float2 fb = __half22float2(*(__half2*)&u.y);
    return make_float4(fa.x, fa.y, fb.x, fb.y);
}

__global__ void k_loss(const __half* __restrict__ enc,
                       const int* __restrict__ user, const int* __restrict__ item,
                       const int* __restrict__ labels,
                       const float* __restrict__ clsW, const float* __restrict__ clsB,
                       const float* __restrict__ duW, const float* __restrict__ duB,
                       const float* __restrict__ diW, const float* __restrict__ diB,
                       const int* __restrict__ numUser, int accBase) {
    __shared__ float sb[8], su[8], si[8];
    int tid = threadIdx.x;
    int wid = tid >> 5, lane = tid & 31;
    int b = blockIdx.x * 8 + wid;
    float bce = 0.f, cu = 0.f, ci = 0.f;
    if (b < BB) {
        int nu = numUser ? numUser[0] : 50000;
        int u = user[b];
        int it = item[b] + nu;
        const uint2* e2 = (const uint2*)enc;
        float4 uf = ld_half4(e2, u * 32 + lane);
        float4 vf = ld_half4(e2, it * 32 + lane);
        float4 cwu = ((const float4*)clsW)[lane];
        float4 cwi = ((const float4*)clsW)[32 + lane];
        float4 dw = ((const float4*)duW)[lane];
        float4 iw = ((const float4*)diW)[lane];
        float z = dot4(uf, cwu) + dot4(vf, cwi);
        float zu = dot4(uf, dw);
        float zi = dot4(vf, iw);
#pragma unroll
        for (int o = 16; o; o >>= 1) {
            z  += __shfl_xor_sync(0xffffffffu, z, o);
            zu += __shfl_xor_sync(0xffffffffu, zu, o);
            zi += __shfl_xor_sync(0xffffffffu, zi, o);
        }
        z += clsB[0];
        zu += duB[0];
        zi += diB[0];
        float y = (float)labels[b];
        float sp_pos = log1pf(expf(-fabsf(z))) + fmaxf(z, 0.f);  // softplus(z)
        float sp_neg = sp_pos - z;                               // softplus(-z)
        bce = y * sp_neg + (1.f - y) * sp_pos;
        cu = 1.f / (1.f + expf(-zu));
        ci = 1.f / (1.f + expf(-zi));
    }
    if (lane == 0) { sb[wid] = bce; su[wid] = cu; si[wid] = ci; }
    __syncthreads();
    if (tid == 0) {
        float B_ = 0.f, U = 0.f, I = 0.f;
#pragma unroll
        for (int i = 0; i < 8; i++) { B_ += sb[i]; U += su[i]; I += si[i]; }
        atomicAdd(&g_acc[accBase + 0], (double)B_);
        atomicAdd(&g_acc[accBase + 1], (double)U);
        atomicAdd(&g_acc[accBase + 2], (double)I);
    }
}

__global__ void k_final(float* out) {
    double invB = 1.0 / (double)BB;
    double clf = (g_acc[0] + g_acc[3]) * invB;
    double dom = fabs(g_acc[1] - g_acc[4]) * invB + fabs(g_acc[2] - g_acc[5]) * invB;
    out[0] = (float)(clf + dom);
}

// ------ launch: two streams, anti-phased domain schedules (R8 footprint) ----
extern "C" void kernel_launch(void* const* d_in, const int* in_sizes, int n_in,
                              void* d_out, int out_size) {
    const float* W1 = (const float*)d_in[2];
    const float* b1 = (const float*)d_in[3];
    const float* W2 = (const float*)d_in[4];
    const float* b2 = (const float*)d_in[5];
    const float* clsW = (const float*)d_in[6];
    const float* clsB = (const float*)d_in[7];
    const float* duW = (const float*)d_in[8];
    const float* duB = (const float*)d_in[9];
    const float* diW = (const float*)d_in[10];
    const float* diB = (const float*)d_in[11];
    const float* feats[2] = {(const float*)d_in[0], (const float*)d_in[1]};
    const int* es[2] = {(const int*)d_in[12], (const int*)d_in[14]};
    const int* ed[2] = {(const int*)d_in[13], (const int*)d_in[15]};
    const int* user[2] = {(const int*)d_in[16], (const int*)d_in[19]};
    const int* item[2] = {(const int*)d_in[17], (const int*)d_in[20]};
    const int* lab[2]  = {(const int*)d_in[18], (const int*)d_in[21]};
    const int* nu[2]   = {(n_in > 22) ? (const int*)d_in[22] : (const int*)0,
                          (n_in > 23) ? (const int*)d_in[23] : (const int*)0};
    float* out = (float*)d_out;

    static cudaStream_t st[2] = {nullptr, nullptr};
    static cudaEvent_t evRoot = nullptr, evDone[2] = {nullptr, nullptr};
    if (!st[0]) {
        cudaStreamCreateWithFlags(&st[0], cudaStreamNonBlocking);
        cudaStreamCreateWithFlags(&st[1], cudaStreamNonBlocking);
        cudaEventCreateWithFlags(&evRoot, cudaEventDisableTiming);
        cudaEventCreateWithFlags(&evDone[0], cudaEventDisableTiming);
        cudaEventCreateWithFlags(&evDone[1], cudaEventDisableTiming);
    }

    __half* tmpB; __half* h1B; __half* hB; float* dinvB;
    int *degB, *rowB, *curB, *colB, *bsB, *boB;
    cudaGetSymbolAddress((void**)&tmpB, g_tmph);
    cudaGetSymbolAddress((void**)&h1B, g_h1);
    cudaGetSymbolAddress((void**)&hB, g_h);
    cudaGetSymbolAddress((void**)&dinvB, g_dinv);
    cudaGetSymbolAddress((void**)&degB, g_deg);
    cudaGetSymbolAddress((void**)&rowB, g_rowptr);
    cudaGetSymbolAddress((void**)&curB, g_cursor);
    cudaGetSymbolAddress((void**)&colB, g_col);
    cudaGetSymbolAddress((void**)&bsB, g_bsum);
    cudaGetSymbolAddress((void**)&boB, g_boff);

    const int TB = 256;
    const int NBLK = (NN + 1023) / 1024;   // 98

    k_zero_acc<<<1, 32>>>();
    cudaEventRecord(evRoot, 0);

    for (int dom = 0; dom < 2; dom++) {
        cudaStream_t s = st[dom];
        cudaStreamWaitEvent(s, evRoot, 0);
        __half* tmp = tmpB + (size_t)dom * NN * DD;
        __half* h1 = h1B + (size_t)dom * NN * DD;
        __half* h = hB + (size_t)dom * NN * DD;
        float* dinv = dinvB + (size_t)dom * NN;
        int* deg = degB + (size_t)dom * NN;
        int* rowptr = rowB + (size_t)dom * (NN + 1);
        int* cursor = curB + (size_t)dom * NN;
        int* col = colB + (size_t)dom * EE;
        int* bsum = bsB + (size_t)dom * 128;
        int* boff = boB + (size_t)dom * 128;

        k_zero_deg<<<(NN + TB - 1) / TB, TB, 0, s>>>(deg);
        k_deg<<<(EE / 4 + TB - 1) / TB, TB, 0, s>>>(ed[dom], deg);
        k_dinv<<<(NN + TB - 1) / TB, TB, 0, s>>>(deg, dinv);

        if (dom == 0) {
            k_scan1<<<NBLK, 1024, 0, s>>>(deg, rowptr, bsum);
            k_scan2<<<1, 32, 0, s>>>(bsum, boff, rowptr, NBLK);
            k_scan3<<<(NN + TB - 1) / TB, TB, 0, s>>>(rowptr, boff, cursor);
            k_fill<<<(EE / 4 + TB - 1) / TB, TB, 0, s>>>(es[dom], ed[dom], cursor, col);
            k_gemm<false><<<(NN + 127) / 128, 256, 0, s>>>(feats[dom], W1, tmp, dinv);
        } else {
            k_gemm<false><<<(NN + 127) / 128, 256, 0, s>>>(feats[dom], W1, tmp, dinv);
            k_scan1<<<NBLK, 1024, 0, s>>>(deg, rowptr, bsum);
            k_scan2<<<1, 32, 0, s>>>(bsum, boff, rowptr, NBLK);
            k_scan3<<<(NN + TB - 1) / TB, TB, 0, s>>>(rowptr, boff, cursor);
            k_fill<<<(EE / 4 + TB - 1) / TB, TB, 0, s>>>(es[dom], ed[dom], cursor, col);
        }

        k_gather<1><<<(NN + 7) / 8, 256, 0, s>>>(tmp, b1, h1, rowptr, col, dinv);
        k_gemm<true><<<(NN + 127) / 128, 256, 0, s>>>(h1, W2, tmp, dinv);
        k_gather<2><<<(NN + 7) / 8, 256, 0, s>>>(tmp, b2, h, rowptr, col, dinv);

        k_loss<<<(BB + 7) / 8, 256, 0, s>>>(h, user[dom], item[dom], lab[dom],
                                            clsW, clsB, duW, duB, diW, diB,
                                            nu[dom], dom * 3);
        cudaEventRecord(evDone[dom], s);
    }

    cudaStreamWaitEvent(0, evDone[0], 0);
    cudaStreamWaitEvent(0, evDone[1], 0);
    k_final<<<1, 1>>>(out);
}

// round 15
// speedup vs baseline: 1.0180x; 1.0180x over previous
#include <cuda_runtime.h>
#include <cuda_fp16.h>
#include <math.h>

#define NN 100000
#define DD 128
#define EE 1600000
#define BB 100000

// ---------------- scratch, double-buffered per domain (no allocations) ------
__device__ __align__(16) __half g_tmph[2][(size_t)NN * DD]; // dinv-scaled GEMM out
__device__ __align__(16) __half g_h1[2][(size_t)NN * DD];   // relu(layer1 out), fp16
__device__ __align__(16) __half g_h[2][(size_t)NN * DD];    // layer2 out (fp16)
__device__ float  g_dinv[2][NN];
__device__ int    g_deg[2][NN];
__device__ int    g_rowptr[2][NN + 1];
__device__ int    g_cursor[2][NN];
__device__ int    g_col[2][EE];
__device__ int    g_bsum[2][128];
__device__ int    g_boff[2][128];
__device__ double g_acc[8];   // bases 0 (src) and 3 (tgt)

// ------- root init: zero BOTH domains' deg + the accumulators, one launch ----
__global__ void k_init0() {
    int i = blockIdx.x * blockDim.x + threadIdx.x;
    if (i < NN) {
        g_deg[0][i] = 0;
        g_deg[1][i] = 0;
    }
    if (i < 8) g_acc[i] = 0.0;
}

__global__ void k_deg(const int* __restrict__ dst, int* __restrict__ deg) {
    int e4 = blockIdx.x * blockDim.x + threadIdx.x;
    if (e4 < EE / 4) {
        int4 d = ((const int4*)dst)[e4];
        atomicAdd(&deg[d.x], 1);
        atomicAdd(&deg[d.y], 1);
        atomicAdd(&deg[d.z], 1);
        atomicAdd(&deg[d.w], 1);
    }
}

// scan phase 1: per-block (1024) exclusive scan + fused dinv computation
__global__ void k_scan1(const int* __restrict__ deg, int* __restrict__ rowptr,
                        int* __restrict__ bsum, float* __restrict__ dinv) {
    __shared__ int s_warp[32];
    int tid = threadIdx.x;
    int lane = tid & 31, wid = tid >> 5;
    int i = blockIdx.x * 1024 + tid;
    int v = (i < NN) ? deg[i] : 0;
    if (i < NN) dinv[i] = rsqrtf((float)v + 1.0f);   // fused (+1 = self loop)
    int x = v;
#pragma unroll
    for (int o = 1; o < 32; o <<= 1) {
        int y = __shfl_up_sync(0xffffffffu, x, o);
        if (lane >= o) x += y;
    }
    if (lane == 31) s_warp[wid] = x;
    __syncthreads();
    if (wid == 0) {
        int w = s_warp[lane];
#pragma unroll
        for (int o = 1; o < 32; o <<= 1) {
            int y = __shfl_up_sync(0xffffffffu, w, o);
            if (lane >= o) w += y;
        }
        s_warp[lane] = w;
    }
    __syncthreads();
    int excl = (wid ? s_warp[wid - 1] : 0) + x - v;
    if (i < NN) rowptr[i] = excl;
    if (tid == 1023) bsum[blockIdx.x] = s_warp[31];
}

__global__ void k_scan2(const int* __restrict__ bsum, int* __restrict__ boff,
                        int* __restrict__ rowptr, int nblk) {
    int lane = threadIdx.x;
    int carry = 0;
    for (int base = 0; base < nblk; base += 32) {
        int idx = base + lane;
        int v = (idx < nblk) ? bsum[idx] : 0;
        int x = v;
#pragma unroll
        for (int o = 1; o < 32; o <<= 1) {
            int y = __shfl_up_sync(0xffffffffu, x, o);
            if (lane >= o) x += y;
        }
        if (idx < nblk) boff[idx] = carry + x - v;
        carry += __shfl_sync(0xffffffffu, x, 31);
    }
    if (lane == 0) rowptr[NN] = carry;
}

__global__ void k_scan3(int* __restrict__ rowptr, const int* __restrict__ boff,
                        int* __restrict__ cursor) {
    int i = blockIdx.x * blockDim.x + threadIdx.x;
    if (i < NN) {
        int r = rowptr[i] + boff[i >> 10];
        rowptr[i] = r;
        cursor[i] = r;
    }
}

__global__ void k_fill(const int* __restrict__ src, const int* __restrict__ dst,
                       int* __restrict__ cursor, int* __restrict__ col) {
    int e4 = blockIdx.x * blockDim.x + threadIdx.x;
    if (e4 < EE / 4) {
        int4 s = ((const int4*)src)[e4];
        int4 d = ((const int4*)dst)[e4];
        int p;
        p = atomicAdd(&cursor[d.x], 1); col[p] = s.x;
        p = atomicAdd(&cursor[d.y], 1); col[p] = s.y;
        p = atomicAdd(&cursor[d.z], 1); col[p] = s.z;
        p = atomicAdd(&cursor[d.w], 1); col[p] = s.w;
    }
}

// ---------------- gather aggregation (R13-proven inner loop) ----------------
__device__ __forceinline__ void acc_row(const uint2* __restrict__ t2, int row, int lane,
                                        float4& acc) {
    uint2 u = t2[row * 32 + lane];
    float2 fa = __half22float2(*(__half2*)&u.x);
    float2 fb = __half22float2(*(__half2*)&u.y);
    acc.x += fa.x; acc.y += fa.y; acc.z += fb.x; acc.w += fb.y;
}

// MODE 1: fp16 + relu (feeds gemm2). MODE 2: fp16 (enc).
template <int MODE>
__global__ __launch_bounds__(256) void k_gather(const __half* __restrict__ tmp,
                                                const float* __restrict__ bias,
                                                void* __restrict__ outv,
                                                const int* __restrict__ rowptr,
                                                const int* __restrict__ col,
                                                const float* __restrict__ dinv) {
    int node = blockIdx.x * 8 + (threadIdx.x >> 5);
    int lane = threadIdx.x & 31;
    if (node >= NN) return;
    int beg = rowptr[node];
    int end = rowptr[node + 1];
    const uint2* t2 = (const uint2*)tmp;
    float4 acc = make_float4(0.f, 0.f, 0.f, 0.f);
    for (int base = beg; base < end; base += 32) {
        int n = min(32, end - base);
        int s = (lane < n) ? col[base + lane] : 0;
        int i = 0;
        for (; i + 4 <= n; i += 4) {
            int a = __shfl_sync(0xffffffffu, s, i);
            int b = __shfl_sync(0xffffffffu, s, i + 1);
            int c = __shfl_sync(0xffffffffu, s, i + 2);
            int d = __shfl_sync(0xffffffffu, s, i + 3);
            acc_row(t2, a, lane, acc);
            acc_row(t2, b, lane, acc);
            acc_row(t2, c, lane, acc);
            acc_row(t2, d, lane, acc);
        }
        for (; i < n; i++) {
            int a = __shfl_sync(0xffffffffu, s, i);
            acc_row(t2, a, lane, acc);
        }
    }
    acc_row(t2, node, lane, acc);   // self-loop term (tmp' pre-scaled)
    float di = dinv[node];
    float4 b = ((const float4*)bias)[lane];
    float4 o;
    o.x = fmaf(di, acc.x, b.x);
    o.y = fmaf(di, acc.y, b.y);
    o.z = fmaf(di, acc.z, b.z);
    o.w = fmaf(di, acc.w, b.w);
    if (MODE == 1) {
        o.x = fmaxf(o.x, 0.f); o.y = fmaxf(o.y, 0.f);
        o.z = fmaxf(o.z, 0.f); o.w = fmaxf(o.w, 0.f);
    }
    uint2 u;
    __half2 h;
    h = __floats2half2_rn(o.x, o.y); u.x = *(unsigned*)&h;
    h = __floats2half2_rn(o.z, o.w); u.y = *(unsigned*)&h;
    ((uint2*)outv)[node * 32 + lane] = u;
}

// ------- GEMM (HFMA2, R13-proven): C_half[r,:] = dinv[r] * (A[r,:] @ W) -----
template <bool AHALF>
__global__ __launch_bounds__(256, 2) void k_gemm(const void* __restrict__ Av,
                                                 const float* __restrict__ W,
                                                 __half* __restrict__ C,
                                                 const float* __restrict__ dinv) {
    __shared__ __half sW[16 * 128];   // [k][n], fp16
    __shared__ __half sA[16 * 136];   // [k][row], fp16, padded stride
    int tid = threadIdx.x;
    int r0 = blockIdx.x * 128;
    int tx = tid & 15, ty = tid >> 4;

    int a_row = tid >> 1, a_k8 = (tid & 1) << 3;
    int w_kr0 = tid >> 5, w_c40 = (tid & 31) << 2;
    int w_kr1 = (tid + 256) >> 5, w_c41 = ((tid + 256) & 31) << 2;

    __half a_st[8];
    float4 w_st[2];

    auto load_chunk = [&](int kk) {
        int gr = r0 + a_row;
        if (AHALF) {
            const __half* Ah = (const __half*)Av;
            uint4 u = make_uint4(0u, 0u, 0u, 0u);
            if (gr < NN) u = *(const uint4*)&Ah[(size_t)gr * DD + kk + a_k8];
            *(uint4*)a_st = u;
        } else {
            const float* Af = (const float*)Av;
            float4 a0 = make_float4(0.f, 0.f, 0.f, 0.f);
            float4 a1 = make_float4(0.f, 0.f, 0.f, 0.f);
            if (gr < NN) {
                a0 = *(const float4*)&Af[(size_t)gr * DD + kk + a_k8];
                a1 = *(const float4*)&Af[(size_t)gr * DD + kk + a_k8 + 4];
            }
            __half2 h;
            h = __floats2half2_rn(a0.x, a0.y); *(__half2*)&a_st[0] = h;
            h = __floats2half2_rn(a0.z, a0.w); *(__half2*)&a_st[2] = h;
            h = __floats2half2_rn(a1.x, a1.y); *(__half2*)&a_st[4] = h;
            h = __floats2half2_rn(a1.z, a1.w); *(__half2*)&a_st[6] = h;
        }
        w_st[0] = *(const float4*)&W[(size_t)(kk + w_kr0) * DD + w_c40];
        w_st[1] = *(const float4*)&W[(size_t)(kk + w_kr1) * DD + w_c41];
    };

    auto store_chunk = [&]() {
#pragma unroll
        for (int j = 0; j < 8; j++) sA[(a_k8 + j) * 136 + a_row] = a_st[j];
        uint2 u;
        __half2 h;
        h = __floats2half2_rn(w_st[0].x, w_st[0].y); u.x = *(unsigned*)&h;
        h = __floats2half2_rn(w_st[0].z, w_st[0].w); u.y = *(unsigned*)&h;
        *(uint2*)&sW[w_kr0 * 128 + w_c40] = u;
        h = __floats2half2_rn(w_st[1].x, w_st[1].y); u.x = *(unsigned*)&h;
        h = __floats2half2_rn(w_st[1].z, w_st[1].w); u.y = *(unsigned*)&h;
        *(uint2*)&sW[w_kr1 * 128 + w_c41] = u;
    };

    float facc[8][8];
#pragma unroll
    for (int m = 0; m < 8; m++)
#pragma unroll
        for (int n = 0; n < 8; n++) facc[m][n] = 0.f;

    load_chunk(0);
    for (int c = 0; c < 8; c++) {
        __syncthreads();
        store_chunk();
        __syncthreads();
        if (c < 7) load_chunk((c + 1) * 16);

        __half2 acc2[8][4];
#pragma unroll
        for (int m = 0; m < 8; m++)
#pragma unroll
            for (int np = 0; np < 4; np++)
                acc2[m][np] = __floats2half2_rn(0.f, 0.f);

#pragma unroll
        for (int k2 = 0; k2 < 16; k2++) {
            uint4 av = *(uint4*)&sA[k2 * 136 + ty * 8];
            uint2 u0 = *(uint2*)&sW[k2 * 128 + tx * 4];
            uint2 u1 = *(uint2*)&sW[k2 * 128 + 64 + tx * 4];
            __half2 wv[4];
            wv[0] = *(__half2*)&u0.x;
            wv[1] = *(__half2*)&u0.y;
            wv[2] = *(__half2*)&u1.x;
            wv[3] = *(__half2*)&u1.y;
            __half2 ap[4];
            ap[0] = *(__half2*)&av.x;
            ap[1] = *(__half2*)&av.y;
            ap[2] = *(__half2*)&av.z;
            ap[3] = *(__half2*)&av.w;
#pragma unroll
            for (int mp = 0; mp < 4; mp++) {
                __half2 alo = __half2half2(__low2half(ap[mp]));
                __half2 ahi = __half2half2(__high2half(ap[mp]));
#pragma unroll
                for (int np = 0; np < 4; np++) {
                    acc2[2 * mp + 0][np] = __hfma2(alo, wv[np], acc2[2 * mp + 0][np]);
                    acc2[2 * mp + 1][np] = __hfma2(ahi, wv[np], acc2[2 * mp + 1][np]);
                }
            }
        }
#pragma unroll
        for (int m = 0; m < 8; m++)
#pragma unroll
            for (int np = 0; np < 4; np++) {
                float2 f = __half22float2(acc2[m][np]);
                facc[m][2 * np + 0] += f.x;
                facc[m][2 * np + 1] += f.y;
            }
    }

#pragma unroll
    for (int m = 0; m < 8; m++) {
        int gr = r0 + ty * 8 + m;
        if (gr < NN) {
            float di = dinv[gr];
            uint2 u0, u1;
            __half2 h;
            h = __floats2half2_rn(facc[m][0] * di, facc[m][1] * di); u0.x = *(unsigned*)&h;
            h = __floats2half2_rn(facc[m][2] * di, facc[m][3] * di); u0.y = *(unsigned*)&h;
            h = __floats2half2_rn(facc[m][4] * di, facc[m][5] * di); u1.x = *(unsigned*)&h;
            h = __floats2half2_rn(facc[m][6] * di, facc[m][7] * di); u1.y = *(unsigned*)&h;
            *(uint2*)&C[(size_t)gr * DD + tx * 4] = u0;
            *(uint2*)&C[(size_t)gr * DD + 64 + tx * 4] = u1;
        }
    }
}

// ---------------- fused loss: one warp per (user,item) pair ----------------
__device__ __forceinline__ float dot4(float4 a, float4 b) {
    return a.x * b.x + a.y * b.y + a.z * b.z + a.w * b.w;
}

__device__ __forceinline__ float4 ld_half4(const uint2* p, int idx) {
    uint2 u = p[idx];
    float2 fa = __half22float2(*(__half2*)&u.x);
    float2 fb = __half22float2(*(__half2*)&u.y);
    return make_float4(fa.x, fa.y, fb.x, fb.y);
}

__global__ void k_loss(const __half* __restrict__ enc,
                       const int* __restrict__ user, const int* __restrict__ item,
                       const int* __restrict__ labels,
                       const float* __restrict__ clsW, const float* __restrict__ clsB,
                       const float* __restrict__ duW, const float* __restrict__ duB,
                       const float* __restrict__ diW, const float* __restrict__ diB,
                       const int* __restrict__ numUser, int accBase) {
    __shared__ float sb[8], su[8], si[8];
    int tid = threadIdx.x;
    int wid = tid >> 5, lane = tid & 31;
    int b = blockIdx.x * 8 + wid;
    float bce = 0.f, cu = 0.f, ci = 0.f;
    if (b < BB) {
        int nu = numUser ? numUser[0] : 50000;
        int u = user[b];
        int it = item[b] + nu;
        const uint2* e2 = (const uint2*)enc;
        float4 uf = ld_half4(e2, u * 32 + lane);
        float4 vf = ld_half4(e2, it * 32 + lane);
        float4 cwu = ((const float4*)clsW)[lane];
        float4 cwi = ((const float4*)clsW)[32 + lane];
        float4 dw = ((const float4*)duW)[lane];
        float4 iw = ((const float4*)diW)[lane];
        float z = dot4(uf, cwu) + dot4(vf, cwi);
        float zu = dot4(uf, dw);
        float zi = dot4(vf, iw);
#pragma unroll
        for (int o = 16; o; o >>= 1) {
            z  += __shfl_xor_sync(0xffffffffu, z, o);
            zu += __shfl_xor_sync(0xffffffffu, zu, o);
            zi += __shfl_xor_sync(0xffffffffu, zi, o);
        }
        z += clsB[0];
        zu += duB[0];
        zi += diB[0];
        float y = (float)labels[b];
        float sp_pos = log1pf(expf(-fabsf(z))) + fmaxf(z, 0.f);  // softplus(z)
        float sp_neg = sp_pos - z;                               // softplus(-z)
        bce = y * sp_neg + (1.f - y) * sp_pos;
        cu = 1.f / (1.f + expf(-zu));
        ci = 1.f / (1.f + expf(-zi));
    }
    if (lane == 0) { sb[wid] = bce; su[wid] = cu; si[wid] = ci; }
    __syncthreads();
    if (tid == 0) {
        float B_ = 0.f, U = 0.f, I = 0.f;
#pragma unroll
        for (int i = 0; i < 8; i++) { B_ += sb[i]; U += su[i]; I += si[i]; }
        atomicAdd(&g_acc[accBase + 0], (double)B_);
        atomicAdd(&g_acc[accBase + 1], (double)U);
        atomicAdd(&g_acc[accBase + 2], (double)I);
    }
}

__global__ void k_final(float* out) {
    double invB = 1.0 / (double)BB;
    double clf = (g_acc[0] + g_acc[3]) * invB;
    double dom = fabs(g_acc[1] - g_acc[4]) * invB + fabs(g_acc[2] - g_acc[5]) * invB;
    out[0] = (float)(clf + dom);
}

// ------ launch: two streams, anti-phased domain schedules ------
extern "C" void kernel_launch(void* const* d_in, const int* in_sizes, int n_in,
                              void* d_out, int out_size) {
    const float* W1 = (const float*)d_in[2];
    const float* b1 = (const float*)d_in[3];
    const float* W2 = (const float*)d_in[4];
    const float* b2 = (const float*)d_in[5];
    const float* clsW = (const float*)d_in[6];
    const float* clsB = (const float*)d_in[7];
    const float* duW = (const float*)d_in[8];
    const float* duB = (const float*)d_in[9];
    const float* diW = (const float*)d_in[10];
    const float* diB = (const float*)d_in[11];
    const float* feats[2] = {(const float*)d_in[0], (const float*)d_in[1]};
    const int* es[2] = {(const int*)d_in[12], (const int*)d_in[14]};
    const int* ed[2] = {(const int*)d_in[13], (const int*)d_in[15]};
    const int* user[2] = {(const int*)d_in[16], (const int*)d_in[19]};
    const int* item[2] = {(const int*)d_in[17], (const int*)d_in[20]};
    const int* lab[2]  = {(const int*)d_in[18], (const int*)d_in[21]};
    const int* nu[2]   = {(n_in > 22) ? (const int*)d_in[22] : (const int*)0,
                          (n_in > 23) ? (const int*)d_in[23] : (const int*)0};
    float* out = (float*)d_out;

    static cudaStream_t st[2] = {nullptr, nullptr};
    static cudaEvent_t evRoot = nullptr, evDone[2] = {nullptr, nullptr};
    if (!st[0]) {
        cudaStreamCreateWithFlags(&st[0], cudaStreamNonBlocking);
        cudaStreamCreateWithFlags(&st[1], cudaStreamNonBlocking);
        cudaEventCreateWithFlags(&evRoot, cudaEventDisableTiming);
        cudaEventCreateWithFlags(&evDone[0], cudaEventDisableTiming);
        cudaEventCreateWithFlags(&evDone[1], cudaEventDisableTiming);
    }

    __half* tmpB; __half* h1B; __half* hB; float* dinvB;
    int *degB, *rowB, *curB, *colB, *bsB, *boB;
    cudaGetSymbolAddress((void**)&tmpB, g_tmph);
    cudaGetSymbolAddress((void**)&h1B, g_h1);
    cudaGetSymbolAddress((void**)&hB, g_h);
    cudaGetSymbolAddress((void**)&dinvB, g_dinv);
    cudaGetSymbolAddress((void**)&degB, g_deg);
    cudaGetSymbolAddress((void**)&rowB, g_rowptr);
    cudaGetSymbolAddress((void**)&curB, g_cursor);
    cudaGetSymbolAddress((void**)&colB, g_col);
    cudaGetSymbolAddress((void**)&bsB, g_bsum);
    cudaGetSymbolAddress((void**)&boB, g_boff);

    const int TB = 256;
    const int NBLK = (NN + 1023) / 1024;   // 98

    k_init0<<<(NN + TB - 1) / TB, TB>>>();   // zero both deg arrays + acc
    cudaEventRecord(evRoot, 0);

    for (int dom = 0; dom < 2; dom++) {
        cudaStream_t s = st[dom];
        cudaStreamWaitEvent(s, evRoot, 0);
        __half* tmp = tmpB + (size_t)dom * NN * DD;
        __half* h1 = h1B + (size_t)dom * NN * DD;
        __half* h = hB + (size_t)dom * NN * DD;
        float* dinv = dinvB + (size_t)dom * NN;
        int* deg = degB + (size_t)dom * NN;
        int* rowptr = rowB + (size_t)dom * (NN + 1);
        int* cursor = curB + (size_t)dom * NN;
        int* col = colB + (size_t)dom * EE;
        int* bsum = bsB + (size_t)dom * 128;
        int* boff = boB + (size_t)dom * 128;

        k_deg<<<(EE / 4 + TB - 1) / TB, TB, 0, s>>>(ed[dom], deg);

        if (dom == 0) {
            k_scan1<<<NBLK, 1024, 0, s>>>(deg, rowptr, bsum, dinv);
            k_scan2<<<1, 32, 0, s>>>(bsum, boff, rowptr, NBLK);
            k_scan3<<<(NN + TB - 1) / TB, TB, 0, s>>>(rowptr, boff, cursor);
            k_fill<<<(EE / 4 + TB - 1) / TB, TB, 0, s>>>(es[dom], ed[dom], cursor, col);
            k_gemm<false><<<(NN + 127) / 128, 256, 0, s>>>(feats[dom], W1, tmp, dinv);
        } else {
            k_scan1<<<NBLK, 1024, 0, s>>>(deg, rowptr, bsum, dinv);
            k_gemm<false><<<(NN + 127) / 128, 256, 0, s>>>(feats[dom], W1, tmp, dinv);
            k_scan2<<<1, 32, 0, s>>>(bsum, boff, rowptr, NBLK);
            k_scan3<<<(NN + TB - 1) / TB, TB, 0, s>>>(rowptr, boff, cursor);
            k_fill<<<(EE / 4 + TB - 1) / TB, TB, 0, s>>>(es[dom], ed[dom], cursor, col);
        }

        k_gather<1><<<(NN + 7) / 8, 256, 0, s>>>(tmp, b1, h1, rowptr, col, dinv);
        k_gemm<true><<<(NN + 127) / 128, 256, 0, s>>>(h1, W2, tmp, dinv);
        k_gather<2><<<(NN + 7) / 8, 256, 0, s>>>(tmp, b2, h, rowptr, col, dinv);

        k_loss<<<(BB + 7) / 8, 256, 0, s>>>(h, user[dom], item[dom], lab[dom],
                                            clsW, clsB, duW, duB, diW, diB,
                                            nu[dom], dom * 3);
        cudaEventRecord(evDone[dom], s);
    }

    cudaStreamWaitEvent(0, evDone[0], 0);
    cudaStreamWaitEvent(0, evDone[1], 0);
    k_final<<<1, 1>>>(out);
}

// round 16
// speedup vs baseline: 1.0186x; 1.0006x over previous
#include <cuda_runtime.h>
#include <cuda_fp16.h>
#include <math.h>

#define NN 100000
#define DD 128
#define EE 1600000
#define BB 100000

// ---------------- scratch, double-buffered per domain (no allocations) ------
__device__ __align__(16) __half g_tmph[2][(size_t)NN * DD]; // dinv-scaled GEMM out
__device__ __align__(16) __half g_h1[2][(size_t)NN * DD];   // relu(layer1 out), fp16
__device__ __align__(16) __half g_h[2][(size_t)NN * DD];    // layer2 out (fp16)
__device__ float  g_dinv[2][NN];
__device__ int    g_deg[2][NN];
__device__ int    g_rowptr[2][NN + 1];
__device__ int    g_cursor[2][NN];
__device__ int    g_col[2][EE];
__device__ int    g_bsum[2][128];
__device__ double g_acc[8];   // bases 0 (src) and 3 (tgt)

// ------- root init: zero BOTH domains' deg + the accumulators, one launch ----
__global__ void k_init0() {
    int i = blockIdx.x * blockDim.x + threadIdx.x;
    if (i < NN) {
        g_deg[0][i] = 0;
        g_deg[1][i] = 0;
    }
    if (i < 8) g_acc[i] = 0.0;
}

__global__ void k_deg(const int* __restrict__ dst, int* __restrict__ deg) {
    int e4 = blockIdx.x * blockDim.x + threadIdx.x;
    if (e4 < EE / 4) {
        int4 d = ((const int4*)dst)[e4];
        atomicAdd(&deg[d.x], 1);
        atomicAdd(&deg[d.y], 1);
        atomicAdd(&deg[d.z], 1);
        atomicAdd(&deg[d.w], 1);
    }
}

// scan phase 1: per-block (1024) exclusive scan + fused dinv computation
__global__ void k_scan1(const int* __restrict__ deg, int* __restrict__ rowptr,
                        int* __restrict__ bsum, float* __restrict__ dinv) {
    __shared__ int s_warp[32];
    int tid = threadIdx.x;
    int lane = tid & 31, wid = tid >> 5;
    int i = blockIdx.x * 1024 + tid;
    int v = (i < NN) ? deg[i] : 0;
    if (i < NN) dinv[i] = rsqrtf((float)v + 1.0f);   // fused (+1 = self loop)
    int x = v;
#pragma unroll
    for (int o = 1; o < 32; o <<= 1) {
        int y = __shfl_up_sync(0xffffffffu, x, o);
        if (lane >= o) x += y;
    }
    if (lane == 31) s_warp[wid] = x;
    __syncthreads();
    if (wid == 0) {
        int w = s_warp[lane];
#pragma unroll
        for (int o = 1; o < 32; o <<= 1) {
            int y = __shfl_up_sync(0xffffffffu, w, o);
            if (lane >= o) w += y;
        }
        s_warp[lane] = w;
    }
    __syncthreads();
    int excl = (wid ? s_warp[wid - 1] : 0) + x - v;
    if (i < NN) rowptr[i] = excl;
    if (tid == 1023) bsum[blockIdx.x] = s_warp[31];
}

// scan phases 2+3 fused: each 256-thread block covers indices with a single
// shared group g = blockIdx>>2 (256 | 1024), so warp 0 redundantly computes
// boff(g) = sum(bsum[0..g-1]); block 0's warp 1 writes rowptr[NN] = total.
__global__ void k_scan23(int* __restrict__ rowptr, const int* __restrict__ bsum,
                         int* __restrict__ cursor, int nblk) {
    __shared__ int s_off;
    int tid = threadIdx.x;
    int g = blockIdx.x >> 2;    // 1024-group index for this block
    if (tid < 32) {
        int p = 0;
        for (int j = tid; j < g; j += 32) p += bsum[j];
#pragma unroll
        for (int o = 16; o; o >>= 1) p += __shfl_xor_sync(0xffffffffu, p, o);
        if (tid == 0) s_off = p;
    } else if (blockIdx.x == 0 && tid < 64) {
        int lane = tid - 32;
        int p = 0;
        for (int j = lane; j < nblk; j += 32) p += bsum[j];
#pragma unroll
        for (int o = 16; o; o >>= 1) p += __shfl_xor_sync(0xffffffffu, p, o);
        if (lane == 0) rowptr[NN] = p;
    }
    __syncthreads();
    int i = blockIdx.x * 256 + tid;
    if (i < NN) {
        int r = rowptr[i] + s_off;
        rowptr[i] = r;
        cursor[i] = r;
    }
}

__global__ void k_fill(const int* __restrict__ src, const int* __restrict__ dst,
                       int* __restrict__ cursor, int* __restrict__ col) {
    int e4 = blockIdx.x * blockDim.x + threadIdx.x;
    if (e4 < EE / 4) {
        int4 s = ((const int4*)src)[e4];
        int4 d = ((const int4*)dst)[e4];
        int p;
        p = atomicAdd(&cursor[d.x], 1); col[p] = s.x;
        p = atomicAdd(&cursor[d.y], 1); col[p] = s.y;
        p = atomicAdd(&cursor[d.z], 1); col[p] = s.z;
        p = atomicAdd(&cursor[d.w], 1); col[p] = s.w;
    }
}

// ---------------- gather aggregation (R13-proven inner loop) ----------------
__device__ __forceinline__ void acc_row(const uint2* __restrict__ t2, int row, int lane,
                                        float4& acc) {
    uint2 u = t2[row * 32 + lane];
    float2 fa = __half22float2(*(__half2*)&u.x);
    float2 fb = __half22float2(*(__half2*)&u.y);
    acc.x += fa.x; acc.y += fa.y; acc.z += fb.x; acc.w += fb.y;
}

// MODE 1: fp16 + relu (feeds gemm2). MODE 2: fp16 (enc).
template <int MODE>
__global__ __launch_bounds__(256) void k_gather(const __half* __restrict__ tmp,
                                                const float* __restrict__ bias,
                                                void* __restrict__ outv,
                                                const int* __restrict__ rowptr,
                                                const int* __restrict__ col,
                                                const float* __restrict__ dinv) {
    int node = blockIdx.x * 8 + (threadIdx.x >> 5);
    int lane = threadIdx.x & 31;
    if (node >= NN) return;
    int beg = rowptr[node];
    int end = rowptr[node + 1];
    const uint2* t2 = (const uint2*)tmp;
    float4 acc = make_float4(0.f, 0.f, 0.f, 0.f);
    for (int base = beg; base < end; base += 32) {
        int n = min(32, end - base);
        int s = (lane < n) ? col[base + lane] : 0;
        int i = 0;
        for (; i + 4 <= n; i += 4) {
            int a = __shfl_sync(0xffffffffu, s, i);
            int b = __shfl_sync(0xffffffffu, s, i + 1);
            int c = __shfl_sync(0xffffffffu, s, i + 2);
            int d = __shfl_sync(0xffffffffu, s, i + 3);
            acc_row(t2, a, lane, acc);
            acc_row(t2, b, lane, acc);
            acc_row(t2, c, lane, acc);
            acc_row(t2, d, lane, acc);
        }
        for (; i < n; i++) {
            int a = __shfl_sync(0xffffffffu, s, i);
            acc_row(t2, a, lane, acc);
        }
    }
    acc_row(t2, node, lane, acc);   // self-loop term (tmp' pre-scaled)
    float di = dinv[node];
    float4 b = ((const float4*)bias)[lane];
    float4 o;
    o.x = fmaf(di, acc.x, b.x);
    o.y = fmaf(di, acc.y, b.y);
    o.z = fmaf(di, acc.z, b.z);
    o.w = fmaf(di, acc.w, b.w);
    if (MODE == 1) {
        o.x = fmaxf(o.x, 0.f); o.y = fmaxf(o.y, 0.f);
        o.z = fmaxf(o.z, 0.f); o.w = fmaxf(o.w, 0.f);
    }
    uint2 u;
    __half2 h;
    h = __floats2half2_rn(o.x, o.y); u.x = *(unsigned*)&h;
    h = __floats2half2_rn(o.z, o.w); u.y = *(unsigned*)&h;
    ((uint2*)outv)[node * 32 + lane] = u;
}

// ------- GEMM (HFMA2, R13-proven): C_half[r,:] = dinv[r] * (A[r,:] @ W) -----
template <bool AHALF>
__global__ __launch_bounds__(256, 2) void k_gemm(const void* __restrict__ Av,
                                                 const float* __restrict__ W,
                                                 __half* __restrict__ C,
                                                 const float* __restrict__ dinv) {
    __shared__ __half sW[16 * 128];   // [k][n], fp16
    __shared__ __half sA[16 * 136];   // [k][row], fp16, padded stride
    int tid = threadIdx.x;
    int r0 = blockIdx.x * 128;
    int tx = tid & 15, ty = tid >> 4;

    int a_row = tid >> 1, a_k8 = (tid & 1) << 3;
    int w_kr0 = tid >> 5, w_c40 = (tid & 31) << 2;
    int w_kr1 = (tid + 256) >> 5, w_c41 = ((tid + 256) & 31) << 2;

    __half a_st[8];
    float4 w_st[2];

    auto load_chunk = [&](int kk) {
        int gr = r0 + a_row;
        if (AHALF) {
            const __half* Ah = (const __half*)Av;
            uint4 u = make_uint4(0u, 0u, 0u, 0u);
            if (gr < NN) u = *(const uint4*)&Ah[(size_t)gr * DD + kk + a_k8];
            *(uint4*)a_st = u;
        } else {
            const float* Af = (const float*)Av;
            float4 a0 = make_float4(0.f, 0.f, 0.f, 0.f);
            float4 a1 = make_float4(0.f, 0.f, 0.f, 0.f);
            if (gr < NN) {
                a0 = *(const float4*)&Af[(size_t)gr * DD + kk + a_k8];
                a1 = *(const float4*)&Af[(size_t)gr * DD + kk + a_k8 + 4];
            }
            __half2 h;
            h = __floats2half2_rn(a0.x, a0.y); *(__half2*)&a_st[0] = h;
            h = __floats2half2_rn(a0.z, a0.w); *(__half2*)&a_st[2] = h;
            h = __floats2half2_rn(a1.x, a1.y); *(__half2*)&a_st[4] = h;
            h = __floats2half2_rn(a1.z, a1.w); *(__half2*)&a_st[6] = h;
        }
        w_st[0] = *(const float4*)&W[(size_t)(kk + w_kr0) * DD + w_c40];
        w_st[1] = *(const float4*)&W[(size_t)(kk + w_kr1) * DD + w_c41];
    };

    auto store_chunk = [&]() {
#pragma unroll
        for (int j = 0; j < 8; j++) sA[(a_k8 + j) * 136 + a_row] = a_st[j];
        uint2 u;
        __half2 h;
        h = __floats2half2_rn(w_st[0].x, w_st[0].y); u.x = *(unsigned*)&h;
        h = __floats2half2_rn(w_st[0].z, w_st[0].w); u.y = *(unsigned*)&h;
        *(uint2*)&sW[w_kr0 * 128 + w_c40] = u;
        h = __floats2half2_rn(w_st[1].x, w_st[1].y); u.x = *(unsigned*)&h;
        h = __floats2half2_rn(w_st[1].z, w_st[1].w); u.y = *(unsigned*)&h;
        *(uint2*)&sW[w_kr1 * 128 + w_c41] = u;
    };

    float facc[8][8];
#pragma unroll
    for (int m = 0; m < 8; m++)
#pragma unroll
        for (int n = 0; n < 8; n++) facc[m][n] = 0.f;

    load_chunk(0);
    for (int c = 0; c < 8; c++) {
        __syncthreads();
        store_chunk();
        __syncthreads();
        if (c < 7) load_chunk((c + 1) * 16);

        __half2 acc2[8][4];
#pragma unroll
        for (int m = 0; m < 8; m++)
#pragma unroll
            for (int np = 0; np < 4; np++)
                acc2[m][np] = __floats2half2_rn(0.f, 0.f);

#pragma unroll
        for (int k2 = 0; k2 < 16; k2++) {
            uint4 av = *(uint4*)&sA[k2 * 136 + ty * 8];
            uint2 u0 = *(uint2*)&sW[k2 * 128 + tx * 4];
            uint2 u1 = *(uint2*)&sW[k2 * 128 + 64 + tx * 4];
            __half2 wv[4];
            wv[0] = *(__half2*)&u0.x;
            wv[1] = *(__half2*)&u0.y;
            wv[2] = *(__half2*)&u1.x;
            wv[3] = *(__half2*)&u1.y;
            __half2 ap[4];
            ap[0] = *(__half2*)&av.x;
            ap[1] = *(__half2*)&av.y;
            ap[2] = *(__half2*)&av.z;
            ap[3] = *(__half2*)&av.w;
#pragma unroll
            for (int mp = 0; mp < 4; mp++) {
                __half2 alo = __half2half2(__low2half(ap[mp]));
                __half2 ahi = __half2half2(__high2half(ap[mp]));
#pragma unroll
                for (int np = 0; np < 4; np++) {
                    acc2[2 * mp + 0][np] = __hfma2(alo, wv[np], acc2[2 * mp + 0][np]);
                    acc2[2 * mp + 1][np] = __hfma2(ahi, wv[np], acc2[2 * mp + 1][np]);
                }
            }
        }
#pragma unroll
        for (int m = 0; m < 8; m++)
#pragma unroll
            for (int np = 0; np < 4; np++) {
                float2 f = __half22float2(acc2[m][np]);
                facc[m][2 * np + 0] += f.x;
                facc[m][2 * np + 1] += f.y;
            }
    }

#pragma unroll
    for (int m = 0; m < 8; m++) {
        int gr = r0 + ty * 8 + m;
        if (gr < NN) {
            float di = dinv[gr];
            uint2 u0, u1;
            __half2 h;
            h = __floats2half2_rn(facc[m][0] * di, facc[m][1] * di); u0.x = *(unsigned*)&h;
            h = __floats2half2_rn(facc[m][2] * di, facc[m][3] * di); u0.y = *(unsigned*)&h;
            h = __floats2half2_rn(facc[m][4] * di, facc[m][5] * di); u1.x = *(unsigned*)&h;
            h = __floats2half2_rn(facc[m][6] * di, facc[m][7] * di); u1.y = *(unsigned*)&h;
            *(uint2*)&C[(size_t)gr * DD + tx * 4] = u0;
            *(uint2*)&C[(size_t)gr * DD + 64 + tx * 4] = u1;
        }
    }
}

// ---------------- fused loss: one warp per (user,item) pair ----------------
__device__ __forceinline__ float dot4(float4 a, float4 b) {
    return a.x * b.x + a.y * b.y + a.z * b.z + a.w * b.w;
}

__device__ __forceinline__ float4 ld_half4(const uint2* p, int idx) {
    uint2 u = p[idx];
    float2 fa = __half22float2(*(__half2*)&u.x);
    float2 fb = __half22float2(*(__half2*)&u.y);
    return make_float4(fa.x, fa.y, fb.x, fb.y);
}

__global__ void k_loss(const __half* __restrict__ enc,
                       const int* __restrict__ user, const int* __restrict__ item,
                       const int* __restrict__ labels,
                       const float* __restrict__ clsW, const float* __restrict__ clsB,
                       const float* __restrict__ duW, const float* __restrict__ duB,
                       const float* __restrict__ diW, const float* __restrict__ diB,
                       const int* __restrict__ numUser, int accBase) {
    __shared__ float sb[8], su[8], si[8];
    int tid = threadIdx.x;
    int wid = tid >> 5, lane = tid & 31;
    int b = blockIdx.x * 8 + wid;
    float bce = 0.f, cu = 0.f, ci = 0.f;
    if (b < BB) {
        int nu = numUser ? numUser[0] : 50000;
        int u = user[b];
        int it = item[b] + nu;
        const uint2* e2 = (const uint2*)enc;
        float4 uf = ld_half4(e2, u * 32 + lane);
        float4 vf = ld_half4(e2, it * 32 + lane);
        float4 cwu = ((const float4*)clsW)[lane];
        float4 cwi = ((const float4*)clsW)[32 + lane];
        float4 dw = ((const float4*)duW)[lane];
        float4 iw = ((const float4*)diW)[lane];
        float z = dot4(uf, cwu) + dot4(vf, cwi);
        float zu = dot4(uf, dw);
        float zi = dot4(vf, iw);
#pragma unroll
        for (int o = 16; o; o >>= 1) {
            z  += __shfl_xor_sync(0xffffffffu, z, o);
            zu += __shfl_xor_sync(0xffffffffu, zu, o);
            zi += __shfl_xor_sync(0xffffffffu, zi, o);
        }
        z += clsB[0];
        zu += duB[0];
        zi += diB[0];
        float y = (float)labels[b];
        float sp_pos = log1pf(expf(-fabsf(z))) + fmaxf(z, 0.f);  // softplus(z)
        float sp_neg = sp_pos - z;                               // softplus(-z)
        bce = y * sp_neg + (1.f - y) * sp_pos;
        cu = 1.f / (1.f + expf(-zu));
        ci = 1.f / (1.f + expf(-zi));
    }
    if (lane == 0) { sb[wid] = bce; su[wid] = cu; si[wid] = ci; }
    __syncthreads();
    if (tid == 0) {
        float B_ = 0.f, U = 0.f, I = 0.f;
#pragma unroll
        for (int i = 0; i < 8; i++) { B_ += sb[i]; U += su[i]; I += si[i]; }
        atomicAdd(&g_acc[accBase + 0], (double)B_);
        atomicAdd(&g_acc[accBase + 1], (double)U);
        atomicAdd(&g_acc[accBase + 2], (double)I);
    }
}

__global__ void k_final(float* out) {
    double invB = 1.0 / (double)BB;
    double clf = (g_acc[0] + g_acc[3]) * invB;
    double dom = fabs(g_acc[1] - g_acc[4]) * invB + fabs(g_acc[2] - g_acc[5]) * invB;
    out[0] = (float)(clf + dom);
}

// ------ launch: two streams, anti-phased domain schedules ------
extern "C" void kernel_launch(void* const* d_in, const int* in_sizes, int n_in,
                              void* d_out, int out_size) {
    const float* W1 = (const float*)d_in[2];
    const float* b1 = (const float*)d_in[3];
    const float* W2 = (const float*)d_in[4];
    const float* b2 = (const float*)d_in[5];
    const float* clsW = (const float*)d_in[6];
    const float* clsB = (const float*)d_in[7];
    const float* duW = (const float*)d_in[8];
    const float* duB = (const float*)d_in[9];
    const float* diW = (const float*)d_in[10];
    const float* diB = (const float*)d_in[11];
    const float* feats[2] = {(const float*)d_in[0], (const float*)d_in[1]};
    const int* es[2] = {(const int*)d_in[12], (const int*)d_in[14]};
    const int* ed[2] = {(const int*)d_in[13], (const int*)d_in[15]};
    const int* user[2] = {(const int*)d_in[16], (const int*)d_in[19]};
    const int* item[2] = {(const int*)d_in[17], (const int*)d_in[20]};
    const int* lab[2]  = {(const int*)d_in[18], (const int*)d_in[21]};
    const int* nu[2]   = {(n_in > 22) ? (const int*)d_in[22] : (const int*)0,
                          (n_in > 23) ? (const int*)d_in[23] : (const int*)0};
    float* out = (float*)d_out;

    static cudaStream_t st[2] = {nullptr, nullptr};
    static cudaEvent_t evRoot = nullptr, evDone[2] = {nullptr, nullptr};
    if (!st[0]) {
        cudaStreamCreateWithFlags(&st[0], cudaStreamNonBlocking);
        cudaStreamCreateWithFlags(&st[1], cudaStreamNonBlocking);
        cudaEventCreateWithFlags(&evRoot, cudaEventDisableTiming);
        cudaEventCreateWithFlags(&evDone[0], cudaEventDisableTiming);
        cudaEventCreateWithFlags(&evDone[1], cudaEventDisableTiming);
    }

    __half* tmpB; __half* h1B; __half* hB; float* dinvB;
    int *degB, *rowB, *curB, *colB, *bsB;
    cudaGetSymbolAddress((void**)&tmpB, g_tmph);
    cudaGetSymbolAddress((void**)&h1B, g_h1);
    cudaGetSymbolAddress((void**)&hB, g_h);
    cudaGetSymbolAddress((void**)&dinvB, g_dinv);
    cudaGetSymbolAddress((void**)&degB, g_deg);
    cudaGetSymbolAddress((void**)&rowB, g_rowptr);
    cudaGetSymbolAddress((void**)&curB, g_cursor);
    cudaGetSymbolAddress((void**)&colB, g_col);
    cudaGetSymbolAddress((void**)&bsB, g_bsum);

    const int TB = 256;
    const int NBLK = (NN + 1023) / 1024;   // 98

    k_init0<<<(NN + TB - 1) / TB, TB>>>();   // zero both deg arrays + acc
    cudaEventRecord(evRoot, 0);

    for (int dom = 0; dom < 2; dom++) {
        cudaStream_t s = st[dom];
        cudaStreamWaitEvent(s, evRoot, 0);
        __half* tmp = tmpB + (size_t)dom * NN * DD;
        __half* h1 = h1B + (size_t)dom * NN * DD;
        __half* h = hB + (size_t)dom * NN * DD;
        float* dinv = dinvB + (size_t)dom * NN;
        int* deg = degB + (size_t)dom * NN;
        int* rowptr = rowB + (size_t)dom * (NN + 1);
        int* cursor = curB + (size_t)dom * NN;
        int* col = colB + (size_t)dom * EE;
        int* bsum = bsB + (size_t)dom * 128;

        k_deg<<<(EE / 4 + TB - 1) / TB, TB, 0, s>>>(ed[dom], deg);

        if (dom == 0) {
            k_scan1<<<NBLK, 1024, 0, s>>>(deg, rowptr, bsum, dinv);
            k_scan23<<<(NN + TB - 1) / TB, TB, 0, s>>>(rowptr, bsum, cursor, NBLK);
            k_fill<<<(EE / 4 + TB - 1) / TB, TB, 0, s>>>(es[dom], ed[dom], cursor, col);
            k_gemm<false><<<(NN + 127) / 128, 256, 0, s>>>(feats[dom], W1, tmp, dinv);
        } else {
            k_scan1<<<NBLK, 1024, 0, s>>>(deg, rowptr, bsum, dinv);
            k_gemm<false><<<(NN + 127) / 128, 256, 0, s>>>(feats[dom], W1, tmp, dinv);
            k_scan23<<<(NN + TB - 1) / TB, TB, 0, s>>>(rowptr, bsum, cursor, NBLK);
            k_fill<<<(EE / 4 + TB - 1) / TB, TB, 0, s>>>(es[dom], ed[dom], cursor, col);
        }

        k_gather<1><<<(NN + 7) / 8, 256, 0, s>>>(tmp, b1, h1, rowptr, col, dinv);
        k_gemm<true><<<(NN + 127) / 128, 256, 0, s>>>(h1, W2, tmp, dinv);
        k_gather<2><<<(NN + 7) / 8, 256, 0, s>>>(tmp, b2, h, rowptr, col, dinv);

        k_loss<<<(BB + 7) / 8, 256, 0, s>>>(h, user[dom], item[dom], lab[dom],
                                            clsW, clsB, duW, duB, diW, diB,
                                            nu[dom], dom * 3);
        cudaEventRecord(evDone[dom], s);
    }

    cudaStreamWaitEvent(0, evDone[0], 0);
    cudaStreamWaitEvent(0, evDone[1], 0);
    k_final<<<1, 1>>>(out);
}